// round 1
// baseline (speedup 1.0000x reference)
#include <cuda_runtime.h>
#include <math.h>

// GELU(x @ W^T + b):  x[8192,512] f32, W[512,512] f32 (row-major [out,in]), b[512]
// Classic SMEM-tiled FFMA GEMM, BM=BN=128, BK=16, 8x8 per-thread tile, 256 threads.

#define GN     8192
#define GK     512
#define GM_OUT 512

#define BM 128
#define BN 128
#define BK 16
#define TM 8
#define TN 8

__global__ __launch_bounds__(256, 2)
void gemm_gelu_kernel(const float* __restrict__ X,
                      const float* __restrict__ W,
                      const float* __restrict__ bias,
                      float* __restrict__ out) {
    // SMEM tiles stored K-outer, transposed so the M/N dim is contiguous.
    __shared__ float As[BK][BM];
    __shared__ float Bs[BK][BN];

    const int bn = blockIdx.x;            // along D_OUT
    const int bm = blockIdx.y;            // along N (rows of X)
    const int tid = threadIdx.x;
    const int tx = tid & 15;              // n direction (16)
    const int ty = tid >> 4;              // m direction (16)

    const int row0 = bm * BM;
    const int col0 = bn * BN;

    float acc[TM][TN];
#pragma unroll
    for (int i = 0; i < TM; i++)
#pragma unroll
        for (int j = 0; j < TN; j++) acc[i][j] = 0.0f;

    for (int kt = 0; kt < GK; kt += BK) {
        // ---- load A tile: X[row0:+128, kt:+16] -> As[k][m] (transposed) ----
        // 128*16 floats = 512 float4 loads; 2 per thread.
#pragma unroll
        for (int l = 0; l < 2; l++) {
            int i  = tid + l * 256;       // float4 index
            int r  = i >> 2;              // 0..127 (tile row)
            int c4 = i & 3;               // 0..3  (float4 within the 16-wide k slab)
            float4 v = *reinterpret_cast<const float4*>(
                X + (size_t)(row0 + r) * GK + kt + c4 * 4);
            As[c4 * 4 + 0][r] = v.x;
            As[c4 * 4 + 1][r] = v.y;
            As[c4 * 4 + 2][r] = v.z;
            As[c4 * 4 + 3][r] = v.w;
        }
        // ---- load B tile: W[col0:+128, kt:+16] -> Bs[k][n] ----
#pragma unroll
        for (int l = 0; l < 2; l++) {
            int i  = tid + l * 256;
            int r  = i >> 2;
            int c4 = i & 3;
            float4 v = *reinterpret_cast<const float4*>(
                W + (size_t)(col0 + r) * GK + kt + c4 * 4);
            Bs[c4 * 4 + 0][r] = v.x;
            Bs[c4 * 4 + 1][r] = v.y;
            Bs[c4 * 4 + 2][r] = v.z;
            Bs[c4 * 4 + 3][r] = v.w;
        }
        __syncthreads();

        // ---- compute ----
#pragma unroll
        for (int k = 0; k < BK; k++) {
            float a[TM], bfr[TN];
            // vectorized SMEM reads (16B aligned: stride 128 floats)
            float4 a0 = *reinterpret_cast<const float4*>(&As[k][ty * TM]);
            float4 a1 = *reinterpret_cast<const float4*>(&As[k][ty * TM + 4]);
            float4 b0 = *reinterpret_cast<const float4*>(&Bs[k][tx * TN]);
            float4 b1 = *reinterpret_cast<const float4*>(&Bs[k][tx * TN + 4]);
            a[0]=a0.x; a[1]=a0.y; a[2]=a0.z; a[3]=a0.w;
            a[4]=a1.x; a[5]=a1.y; a[6]=a1.z; a[7]=a1.w;
            bfr[0]=b0.x; bfr[1]=b0.y; bfr[2]=b0.z; bfr[3]=b0.w;
            bfr[4]=b1.x; bfr[5]=b1.y; bfr[6]=b1.z; bfr[7]=b1.w;
#pragma unroll
            for (int i = 0; i < TM; i++)
#pragma unroll
                for (int j = 0; j < TN; j++)
                    acc[i][j] = fmaf(a[i], bfr[j], acc[i][j]);
        }
        __syncthreads();
    }

    // ---- epilogue: + bias, exact GELU, vectorized store ----
    float bv[TN];
    {
        float4 b0 = *reinterpret_cast<const float4*>(bias + col0 + tx * TN);
        float4 b1 = *reinterpret_cast<const float4*>(bias + col0 + tx * TN + 4);
        bv[0]=b0.x; bv[1]=b0.y; bv[2]=b0.z; bv[3]=b0.w;
        bv[4]=b1.x; bv[5]=b1.y; bv[6]=b1.z; bv[7]=b1.w;
    }
    const float kInvSqrt2 = 0.70710678118654752440f;
#pragma unroll
    for (int i = 0; i < TM; i++) {
        int m = row0 + ty * TM + i;
        float g[TN];
#pragma unroll
        for (int j = 0; j < TN; j++) {
            float v = acc[i][j] + bv[j];
            g[j] = 0.5f * v * (1.0f + erff(v * kInvSqrt2));
        }
        float4* o = reinterpret_cast<float4*>(out + (size_t)m * GM_OUT + col0 + tx * TN);
        o[0] = make_float4(g[0], g[1], g[2], g[3]);
        o[1] = make_float4(g[4], g[5], g[6], g[7]);
    }
}

extern "C" void kernel_launch(void* const* d_in, const int* in_sizes, int n_in,
                              void* d_out, int out_size) {
    // metadata order: x, adj (unused), W, b, a (unused)
    const float* X    = (const float*)d_in[0];
    const float* W    = (const float*)d_in[2];
    const float* bias = (const float*)d_in[3];
    float* out        = (float*)d_out;

    dim3 grid(GM_OUT / BN, GN / BM);   // (4, 64)
    dim3 block(256);
    gemm_gelu_kernel<<<grid, block>>>(X, W, bias, out);
}

// round 3
// speedup vs baseline: 2.2005x; 2.2005x over previous
#include <cuda_runtime.h>
#include <cuda_bf16.h>
#include <cstdint>
#include <math.h>

// GELU(x @ W^T + b) via split-bf16 (hi/lo, 3-pass Markidis) mma.sync HMMA GEMM.
// x[8192,512] f32, W[512,512] f32 row-major [out,in], b[512] f32, out f32.
// (tcgen05 unavailable: harness PTX target is compute_103, not 103a.)

#define GN   8192
#define GK   512
#define GOUT 512
#define BM   128
#define BN   128
#define KC   32              // f32 K elements per iteration
#define NIT  (GK / KC)       // 16
#define LDT  40              // smem row stride in bf16 (32 data + 8 pad = 80B)

__device__ __forceinline__ uint32_t smem_u32(const void* p) {
    return (uint32_t)__cvta_generic_to_shared(p);
}
__device__ __forceinline__ void ldmx4(uint32_t* r, uint32_t addr) {
    asm volatile("ldmatrix.sync.aligned.m8n8.x4.shared.b16 {%0,%1,%2,%3}, [%4];"
                 : "=r"(r[0]), "=r"(r[1]), "=r"(r[2]), "=r"(r[3]) : "r"(addr));
}
__device__ __forceinline__ void mma16816(float* c, const uint32_t* a, const uint32_t* b) {
    asm volatile(
        "mma.sync.aligned.m16n8k16.row.col.f32.bf16.bf16.f32 "
        "{%0,%1,%2,%3}, {%4,%5,%6,%7}, {%8,%9}, {%0,%1,%2,%3};"
        : "+f"(c[0]), "+f"(c[1]), "+f"(c[2]), "+f"(c[3])
        : "r"(a[0]), "r"(a[1]), "r"(a[2]), "r"(a[3]), "r"(b[0]), "r"(b[1]));
}
// split one float4 into bf16-hi pair-of-pairs and bf16-lo
__device__ __forceinline__ void split4(float4 v, uint2& hv, uint2& lv) {
    __nv_bfloat16 h0 = __float2bfloat16(v.x);
    __nv_bfloat16 h1 = __float2bfloat16(v.y);
    __nv_bfloat16 h2 = __float2bfloat16(v.z);
    __nv_bfloat16 h3 = __float2bfloat16(v.w);
    __nv_bfloat16 l0 = __float2bfloat16(v.x - __bfloat162float(h0));
    __nv_bfloat16 l1 = __float2bfloat16(v.y - __bfloat162float(h1));
    __nv_bfloat16 l2 = __float2bfloat16(v.z - __bfloat162float(h2));
    __nv_bfloat16 l3 = __float2bfloat16(v.w - __bfloat162float(h3));
    __nv_bfloat162 hp0(h0, h1), hp1(h2, h3), lp0(l0, l1), lp1(l2, l3);
    hv = make_uint2(*reinterpret_cast<uint32_t*>(&hp0), *reinterpret_cast<uint32_t*>(&hp1));
    lv = make_uint2(*reinterpret_cast<uint32_t*>(&lp0), *reinterpret_cast<uint32_t*>(&lp1));
}

__global__ __launch_bounds__(256)
void gemm_bf16x3_gelu(const float* __restrict__ X,
                      const float* __restrict__ W,
                      const float* __restrict__ bias,
                      float* __restrict__ out) {
    __shared__ __nv_bfloat16 Ahi[BM * LDT], Alo[BM * LDT];
    __shared__ __nv_bfloat16 Bhi[BN * LDT], Blo[BN * LDT];

    const int tid = threadIdx.x;
    const int wid = tid >> 5;
    const int lid = tid & 31;
    const int col0 = blockIdx.x * BN;
    const int row0 = blockIdx.y * BM;

    const int wm = wid >> 1;          // 0..3 -> M offset wm*32
    const int wn = wid & 1;           // 0..1 -> N offset wn*64
    const int m0 = wm * 32;
    const int n0 = wn * 64;

    const int lrow  = lid & 15;       // ldmatrix row within 16
    const int lkoff = (lid >> 4) * 8; // ldmatrix k element offset (0/8)

    float acc[2][8][4];
#pragma unroll
    for (int mf = 0; mf < 2; mf++)
#pragma unroll
        for (int nf = 0; nf < 8; nf++)
#pragma unroll
            for (int q = 0; q < 4; q++) acc[mf][nf][q] = 0.0f;

    for (int it = 0; it < NIT; it++) {
        const int kt = it * KC;
        __syncthreads();   // protect smem reuse from previous iter's reads
        // ---- load + split: X/W [128 rows x 32 f32] -> hi/lo bf16 smem ----
#pragma unroll
        for (int t = 0; t < 4; t++) {
            const int i  = tid + t * 256;  // 0..1023 float4 index
            const int r  = i >> 3;         // 0..127
            const int c4 = i & 7;          // 0..7
            uint2 hv, lv;
            float4 vx = *reinterpret_cast<const float4*>(
                X + (size_t)(row0 + r) * GK + kt + c4 * 4);
            split4(vx, hv, lv);
            *reinterpret_cast<uint2*>(&Ahi[r * LDT + c4 * 4]) = hv;
            *reinterpret_cast<uint2*>(&Alo[r * LDT + c4 * 4]) = lv;
            float4 vw = *reinterpret_cast<const float4*>(
                W + (size_t)(col0 + r) * GK + kt + c4 * 4);
            split4(vw, hv, lv);
            *reinterpret_cast<uint2*>(&Bhi[r * LDT + c4 * 4]) = hv;
            *reinterpret_cast<uint2*>(&Blo[r * LDT + c4 * 4]) = lv;
        }
        __syncthreads();

        // ---- compute: 2 k-steps of 16 ----
#pragma unroll
        for (int ks = 0; ks < 2; ks++) {
            const int kb = ks * 16 + lkoff;
            uint32_t ah[2][4], al[2][4];
#pragma unroll
            for (int mf = 0; mf < 2; mf++) {
                ldmx4(ah[mf], smem_u32(&Ahi[(m0 + mf * 16 + lrow) * LDT + kb]));
                ldmx4(al[mf], smem_u32(&Alo[(m0 + mf * 16 + lrow) * LDT + kb]));
            }
            uint32_t bh[8][2], bl[8][2];
#pragma unroll
            for (int nf2 = 0; nf2 < 4; nf2++) {
                uint32_t r4[4];
                ldmx4(r4, smem_u32(&Bhi[(n0 + nf2 * 16 + lrow) * LDT + kb]));
                bh[nf2 * 2][0] = r4[0]; bh[nf2 * 2 + 1][0] = r4[1];
                bh[nf2 * 2][1] = r4[2]; bh[nf2 * 2 + 1][1] = r4[3];
                ldmx4(r4, smem_u32(&Blo[(n0 + nf2 * 16 + lrow) * LDT + kb]));
                bl[nf2 * 2][0] = r4[0]; bl[nf2 * 2 + 1][0] = r4[1];
                bl[nf2 * 2][1] = r4[2]; bl[nf2 * 2 + 1][1] = r4[3];
            }
#pragma unroll
            for (int mf = 0; mf < 2; mf++)
#pragma unroll
                for (int nf = 0; nf < 8; nf++) {
                    mma16816(acc[mf][nf], ah[mf], bh[nf]);  // hi*hi
                    mma16816(acc[mf][nf], ah[mf], bl[nf]);  // hi*lo
                    mma16816(acc[mf][nf], al[mf], bh[nf]);  // lo*hi
                }
        }
    }

    // ---- epilogue: +bias, exact GELU, store ----
    const float kInvSqrt2 = 0.70710678118654752440f;
    const int lr = lid >> 2;          // 0..7
    const int lc = (lid & 3) * 2;     // 0,2,..6
#pragma unroll
    for (int mf = 0; mf < 2; mf++) {
#pragma unroll
        for (int nf = 0; nf < 8; nf++) {
            const int col = col0 + n0 + nf * 8 + lc;
            const float2 bv = *reinterpret_cast<const float2*>(bias + col);
            const int ra = row0 + m0 + mf * 16 + lr;
#pragma unroll
            for (int half = 0; half < 2; half++) {
                const int r = ra + half * 8;
                float v0 = acc[mf][nf][half * 2 + 0] + bv.x;
                float v1 = acc[mf][nf][half * 2 + 1] + bv.y;
                float g0 = 0.5f * v0 * (1.0f + erff(v0 * kInvSqrt2));
                float g1 = 0.5f * v1 * (1.0f + erff(v1 * kInvSqrt2));
                *reinterpret_cast<float2*>(out + (size_t)r * GOUT + col) =
                    make_float2(g0, g1);
            }
        }
    }
}

extern "C" void kernel_launch(void* const* d_in, const int* in_sizes, int n_in,
                              void* d_out, int out_size) {
    // metadata order: x, adj (unused), W, b, a (unused)
    const float* X    = (const float*)d_in[0];
    const float* W    = (const float*)d_in[2];
    const float* bias = (const float*)d_in[3];
    float* out        = (float*)d_out;

    dim3 grid(GOUT / BN, GN / BM);   // (4, 64)
    gemm_bf16x3_gelu<<<grid, 256>>>(X, W, bias, out);
}